// round 13
// baseline (speedup 1.0000x reference)
#include <cuda_runtime.h>
#include <cstdint>

// Problem shape (fixed by reference): B=32, C=256, H=64, W=64
// in:  d_in[0] = data_in   [B,C,H,W] f32  (33,554,432 elems)
//      d_in[1] = td_energy [C]       f32  (256)
//      d_in[2] = td_hist   [100,100] f32  (10,000)
// out: [ data_in copy | energy+meanabs | hist+1 ]  (f32)
//
// CONVERGED (12 rounds): workload is pinned at the HBM sustained floor —
// 268 MB of mandatory traffic per replay at ~5.9 TB/s sustained ≈ 45.5us.
// All structural variants (wave scheduling, persistence, atomic/fence
// schemes, node count, MLP depth, 16B vs 32B accesses, and three L2
// cross-replay residency schemes) measured within ±0.3us of this floor.
// This is the best-measured configuration: one plane per block,
// front-batched 256-bit LDG/STG, packed-abs reduce, one fire-and-forget
// atomic per block, side-tasks in a micro node.

static constexpr int B = 32;
static constexpr int C = 256;
static constexpr int HW = 64 * 64;              // 4096 floats per plane
static constexpr int PLANES = B * C;            // 8192
static constexpr long long N_DATA = (long long)PLANES * HW;  // 33,554,432
static constexpr float INV_N = 1.0f / (float)(B * HW);       // 1/131072
static constexpr int HIST_N = 10000;

struct f8 { float v[8]; };

__device__ __forceinline__ f8 ldg8(const float* p) {
    f8 r;
    asm volatile(
        "ld.global.nc.v8.b32 {%0,%1,%2,%3,%4,%5,%6,%7}, [%8];"
        : "=f"(r.v[0]), "=f"(r.v[1]), "=f"(r.v[2]), "=f"(r.v[3]),
          "=f"(r.v[4]), "=f"(r.v[5]), "=f"(r.v[6]), "=f"(r.v[7])
        : "l"(p));
    return r;
}
__device__ __forceinline__ void stg8(float* p, const f8& r) {
    asm volatile(
        "st.global.v8.b32 [%0], {%1,%2,%3,%4,%5,%6,%7,%8};"
        :: "l"(p),
           "f"(r.v[0]), "f"(r.v[1]), "f"(r.v[2]), "f"(r.v[3]),
           "f"(r.v[4]), "f"(r.v[5]), "f"(r.v[6]), "f"(r.v[7])
        : "memory");
}

// |a| + |b| accumulated via packed f32x2: one 64-bit sign-mask AND + one
// packed FADD per pair (~half the reduce instruction stream vs scalar).
__device__ __forceinline__ void acc_abs2(unsigned long long& acc,
                                         float a, float b) {
    unsigned long long p;
    asm("mov.b64 %0, {%1, %2};" : "=l"(p) : "f"(a), "f"(b));
    p &= 0x7FFFFFFF7FFFFFFFull;                       // clear both signs
    asm("add.rn.f32x2 %0, %0, %1;" : "+l"(acc) : "l"(p));
}

// Node 1: seed out_energy (base values; bulk atomicAdds on top, resetting
// the accumulator every replay -> deterministic) + hist (+1).
__global__ void init_small(const float* __restrict__ td_energy,
                           const float* __restrict__ td_hist,
                           float* __restrict__ out_energy,
                           float* __restrict__ out_hist) {
    int i = blockIdx.x * 256 + threadIdx.x;
    if (i < C)      out_energy[i] = td_energy[i];
    if (i < HIST_N) out_hist[i]   = td_hist[i] + 1.0f;
}

// Node 2: bulk copy + reduce. One plane per block, 256 threads x 2 x 32B,
// loads front-batched (2 independent 256-bit LDG -> MLP), stores after.
__global__ __launch_bounds__(256) void fused_bulk(
    const float* __restrict__ in,
    float* __restrict__ out,
    float* __restrict__ out_energy) {

    const int bid = blockIdx.x;            // 0..8191 = b*C + c
    const int c  = bid & (C - 1);          // channel
    const int tid = threadIdx.x;

    const size_t base = ((size_t)bid << 12);   // plane base in floats

    // ---- front-batched loads: 2 independent 256-bit LDG ----
    f8 v0 = ldg8(in + base + tid * 8);
    f8 v1 = ldg8(in + base + 2048 + tid * 8);

    // ---- stores: 256-bit STG ----
    stg8(out + base + tid * 8,        v0);
    stg8(out + base + 2048 + tid * 8, v1);

    // ---- reduce |x| via packed pairs ----
    unsigned long long acc = 0;            // two f32 partial sums
#pragma unroll
    for (int j = 0; j < 8; j += 2) {
        acc_abs2(acc, v0.v[j], v0.v[j + 1]);
        acc_abs2(acc, v1.v[j], v1.v[j + 1]);
    }
    float lo, hi;
    asm("mov.b64 {%0, %1}, %2;" : "=f"(lo), "=f"(hi) : "l"(acc));
    float s = lo + hi;

#pragma unroll
    for (int o = 16; o > 0; o >>= 1)
        s += __shfl_xor_sync(0xffffffffu, s, o);

    __shared__ float ws[8];
    if ((tid & 31) == 0) ws[tid >> 5] = s;
    __syncthreads();

    if (tid == 0) {
        s = ws[0];
#pragma unroll
        for (int w = 1; w < 8; w++) s += ws[w];
        atomicAdd(&out_energy[c], s * INV_N);   // fire-and-forget
    }
}

extern "C" void kernel_launch(void* const* d_in, const int* in_sizes, int n_in,
                              void* d_out, int out_size) {
    const float* data_in   = (const float*)d_in[0];
    const float* td_energy = (const float*)d_in[1];
    const float* td_hist   = (const float*)d_in[2];

    float* out        = (float*)d_out;
    float* out_energy = out + N_DATA;
    float* out_hist   = out_energy + C;

    init_small<<<(HIST_N + 255) / 256, 256>>>(td_energy, td_hist,
                                              out_energy, out_hist);
    fused_bulk<<<PLANES, 256>>>(data_in, out, out_energy);
}

// round 14
// speedup vs baseline: 1.0077x; 1.0077x over previous
#include <cuda_runtime.h>
#include <cstdint>

// Problem shape (fixed by reference): B=32, C=256, H=64, W=64
// in:  d_in[0] = data_in   [B,C,H,W] f32  (33,554,432 elems)
//      d_in[1] = td_energy [C]       f32  (256)
//      d_in[2] = td_hist   [100,100] f32  (10,000)
// out: [ data_in copy | energy+meanabs | hist+1 ]  (f32)
//
// FINAL (converged after 13 rounds): the workload is pinned at the HBM
// sustained floor — 268 MB of mandatory traffic per replay at ~5.9 TB/s
// sustained ≈ 45.5us total. Fourteen structurally distinct configurations
// (wave scheduling, persistent grids, atomic/fence/acq_rel schemes, node
// count, MLP depth, 16B vs 32B accesses, packed-abs reduce, and three L2
// cross-replay residency schemes) all measured within [45.53, 45.89]us.
// This is the best-measured configuration (45.536us, 5977 GB/s in-kernel):
// one plane per block, 4x float4 copy+reduce, warp/smem reduce, one
// fire-and-forget scaled atomicAdd per block, side-tasks in a micro node.

static constexpr int B = 32;
static constexpr int C = 256;
static constexpr int HW = 64 * 64;          // 4096 floats per plane
static constexpr int PLANES = B * C;        // 8192
static constexpr long long N_DATA = (long long)PLANES * HW;  // 33,554,432
static constexpr float INV_N = 1.0f / (float)(B * HW);       // 1/131072
static constexpr int HIST_N = 10000;

// Node 1: seed out_energy (base values; bulk atomicAdds on top, resetting
// the accumulator every replay -> deterministic) + hist (+1).
__global__ void init_small(const float* __restrict__ td_energy,
                           const float* __restrict__ td_hist,
                           float* __restrict__ out_energy,
                           float* __restrict__ out_hist) {
    int i = blockIdx.x * blockDim.x + threadIdx.x;
    if (i < C)      out_energy[i] = td_energy[i];
    if (i < HIST_N) out_hist[i]   = td_hist[i] + 1.0f;
}

// Node 2: one block per (b,c) plane: copy 4096 floats (float4 vectorized)
// and accumulate sum(|x|); scaled partial atomically added to out_energy[c].
__global__ __launch_bounds__(256) void copy_reduce(
    const float4* __restrict__ in,
    float4* __restrict__ out,
    float* __restrict__ out_energy) {

    const int plane = blockIdx.x;           // b*C + c
    const int c = plane & (C - 1);
    const size_t base = (size_t)plane * (HW / 4);   // float4 units

    const float4* src = in + base;
    float4* dst = out + base;

    float s = 0.0f;
#pragma unroll
    for (int i = 0; i < 4; i++) {
        float4 v = src[threadIdx.x + i * 256];
        dst[threadIdx.x + i * 256] = v;
        s += fabsf(v.x) + fabsf(v.y) + fabsf(v.z) + fabsf(v.w);
    }

    // warp reduce
#pragma unroll
    for (int o = 16; o > 0; o >>= 1)
        s += __shfl_xor_sync(0xffffffffu, s, o);

    __shared__ float ws[8];
    if ((threadIdx.x & 31) == 0) ws[threadIdx.x >> 5] = s;
    __syncthreads();

    if (threadIdx.x == 0) {
        s = ws[0];
#pragma unroll
        for (int w = 1; w < 8; w++) s += ws[w];
        atomicAdd(&out_energy[c], s * INV_N);   // fire-and-forget
    }
}

extern "C" void kernel_launch(void* const* d_in, const int* in_sizes, int n_in,
                              void* d_out, int out_size) {
    const float* data_in   = (const float*)d_in[0];
    const float* td_energy = (const float*)d_in[1];
    const float* td_hist   = (const float*)d_in[2];

    float* out        = (float*)d_out;
    float* out_energy = out + N_DATA;
    float* out_hist   = out_energy + C;

    init_small<<<(HIST_N + 255) / 256, 256>>>(td_energy, td_hist,
                                              out_energy, out_hist);
    copy_reduce<<<PLANES, 256>>>((const float4*)data_in, (float4*)out,
                                 out_energy);
}